// round 14
// baseline (speedup 1.0000x reference)
#include <cuda_runtime.h>
#include <math.h>
#include <stdint.h>

#define N_NODES 50000
#define N_EDGES 800000
#define HID 64
#define ELLW 64

// ---------------- scratch (device globals) ----------------
__device__ float g_h[N_NODES*HID];
__device__ float g_feat[N_NODES*HID];
__device__ float g_fcat[N_NODES*4*HID];
__device__ float g_el[N_NODES];
__device__ float g_er[N_NODES];
__device__ unsigned char g_mask[N_NODES*ELLW];
__device__ int g_deg[N_NODES];
__device__ int g_ell[N_NODES*ELLW];

// ---------------- tf32 split helpers ----------------
__device__ __forceinline__ void split32(float x, uint32_t& hi, uint32_t& lo){
  uint32_t xb = __float_as_uint(x);
  hi = xb & 0xFFFFE000u;                       // exact tf32 (truncation)
  lo = __float_as_uint(x - __uint_as_float(hi));
}
__device__ __forceinline__ void mma8(float* c, const uint32_t* a, const uint32_t* b){
  asm(
    "mma.sync.aligned.m16n8k8.row.col.f32.tf32.tf32.f32 "
    "{%0,%1,%2,%3}, {%4,%5,%6,%7}, {%8,%9}, {%0,%1,%2,%3};"
    : "+f"(c[0]), "+f"(c[1]), "+f"(c[2]), "+f"(c[3])
    : "r"(a[0]), "r"(a[1]), "r"(a[2]), "r"(a[3]), "r"(b[0]), "r"(b[1]));
}

// ---------------- tensor-core GEMM (mma.sync tf32 split), 64-row tile ----------------
// C[n,64] = act(A[n,K] @ W[K,64]); tile 64x64; K-chunk 32; 8 warps (4 M x 2 N),
// each warp 16 rows x 32 cols. Grid = 2x blocks of the 128-row version.
// ACT: 0=none, 1=tanh, 2=bias+relu
// MODE: 0=plain store; 1=store + el/er dots; 2=NO store, final dot w2 -> out[n]
template<int K, int ACT, int MODE>
__global__ void __launch_bounds__(256, 4) tcg_k(const float* __restrict__ A, int lda,
    const float* __restrict__ W, const float* __restrict__ bias,
    float* __restrict__ out, int n,
    const float* __restrict__ al, const float* __restrict__ ar,
    float* __restrict__ el, float* __restrict__ er,
    const float* __restrict__ w2, const float* __restrict__ b2)
{
  __shared__ float As[64*32];    // A chunk, k-XOR-swizzled per row
  __shared__ float Ws[64*32];    // W^T chunk: Ws[c][k], k-XOR-swizzled per c-row
  int tid = threadIdx.x, lane = tid & 31, wid = tid >> 5;
  int wm = wid & 3, wn = wid >> 2;     // warp grid 4 (M, 16 rows) x 2 (N, 32 cols)
  int gid = lane >> 2, tig = lane & 3;
  int row0 = blockIdx.x * 64;

  float acc[4][4];
  #pragma unroll
  for (int nt = 0; nt < 4; ++nt)
    #pragma unroll
    for (int i = 0; i < 4; ++i) acc[nt][i] = 0.f;

  for (int kc = 0; kc < K; kc += 32) {
    __syncthreads();
    // A fill: 64 rows x 32 k = 512 float4
    #pragma unroll
    for (int j = 0; j < 2; ++j) {
      int idx = tid + 256*j;
      int r = idx >> 3, kq = (idx & 7) * 4;
      float4 v = make_float4(0.f,0.f,0.f,0.f);
      int gr = row0 + r;
      if (gr < n) v = *(const float4*)(A + (size_t)gr*lda + kc + kq);
      *(float4*)&As[r*32 + (kq ^ (4*(r & 7)))] = v;
    }
    // W fill: transpose W[k][c] -> Ws[c][k], swizzled; 32 k x 64 c = 512 float4
    #pragma unroll
    for (int j = 0; j < 2; ++j) {
      int idx = tid + 256*j;
      int k = idx >> 4, cq = (idx & 15) * 4;
      float4 v = *(const float4*)(W + (size_t)(kc + k)*64 + cq);
      Ws[(cq+0)*32 + (k ^ (4*((cq+0) & 7)))] = v.x;
      Ws[(cq+1)*32 + (k ^ (4*((cq+1) & 7)))] = v.y;
      Ws[(cq+2)*32 + (k ^ (4*((cq+2) & 7)))] = v.z;
      Ws[(cq+3)*32 + (k ^ (4*((cq+3) & 7)))] = v.w;
    }
    __syncthreads();

    #pragma unroll
    for (int ks = 0; ks < 4; ++ks) {
      int k0 = ks * 8;
      // A fragment: rows wm*16 + gid, +8
      int r = wm*16 + gid;
      int m = 4*(r & 7);                 // (r+8)&7 == r&7
      uint32_t ah[4], alo[4];
      split32(As[r*32     + ((k0 + tig)     ^ m)], ah[0], alo[0]);
      split32(As[(r+8)*32 + ((k0 + tig)     ^ m)], ah[1], alo[1]);
      split32(As[r*32     + ((k0 + tig + 4) ^ m)], ah[2], alo[2]);
      split32(As[(r+8)*32 + ((k0 + tig + 4) ^ m)], ah[3], alo[3]);
      #pragma unroll
      for (int nt = 0; nt < 4; ++nt) {
        int c = wn*32 + nt*8 + gid;
        int mw = 4*(c & 7);
        uint32_t bh[2], blo[2];
        split32(Ws[c*32 + ((k0 + tig)     ^ mw)], bh[0], blo[0]);
        split32(Ws[c*32 + ((k0 + tig + 4) ^ mw)], bh[1], blo[1]);
        mma8(acc[nt], ah,  bh);
        mma8(acc[nt], ah,  blo);
        mma8(acc[nt], alo, bh);
      }
    }
  }

  // reduction scratch overlays As (done reading it)
  float* redl = As;
  float* redr = As + 64;
  if (MODE == 1 || MODE == 2) {
    __syncthreads();
    if (tid < 64) { redl[tid] = 0.f; redr[tid] = 0.f; }
    __syncthreads();
  }

  #pragma unroll
  for (int h = 0; h < 2; ++h) {
    int lr = wm*16 + 8*h + gid;
    int r = row0 + lr;
    float pl = 0.f, pr = 0.f;
    #pragma unroll
    for (int nt = 0; nt < 4; ++nt) {
      float o0 = acc[nt][2*h], o1 = acc[nt][2*h + 1];
      int c0 = wn*32 + nt*8 + 2*tig;
      if (ACT == 1) { o0 = tanhf(o0); o1 = tanhf(o1); }
      if (ACT == 2) { o0 = fmaxf(o0 + bias[c0], 0.f); o1 = fmaxf(o1 + bias[c0+1], 0.f); }
      if (MODE != 2 && r < n)
        *(float2*)(out + (size_t)r*64 + c0) = make_float2(o0, o1);
      if (MODE == 1) {
        pl += o0*al[c0] + o1*al[c0+1];
        pr += o0*ar[c0] + o1*ar[c0+1];
      }
      if (MODE == 2) pl += o0*w2[c0] + o1*w2[c0+1];
    }
    if (MODE == 1 || MODE == 2) {
      pl += __shfl_xor_sync(0xffffffffu, pl, 1);
      pl += __shfl_xor_sync(0xffffffffu, pl, 2);
      if (MODE == 1) {
        pr += __shfl_xor_sync(0xffffffffu, pr, 1);
        pr += __shfl_xor_sync(0xffffffffu, pr, 2);
      }
      if (tig == 0) {
        atomicAdd(&redl[lr], pl);
        if (MODE == 1) atomicAdd(&redr[lr], pr);
      }
    }
  }

  if (MODE == 1 || MODE == 2) {
    __syncthreads();
    if (tid < 64) {
      int r = row0 + tid;
      if (r < n) {
        if (MODE == 1) { el[r] = redl[tid]; er[r] = redr[tid]; }
        else           out[r] = fmaxf(redl[tid] + b2[0], 0.f);
      }
    }
  }
}

// ---------------- ELL build ----------------
__global__ void zero_deg_k(int n){
  int i = blockIdx.x*blockDim.x + threadIdx.x;
  if (i < n) g_deg[i] = 0;
}
__global__ void build_k(const int* __restrict__ src, const int* __restrict__ dst, int e){
  int i = 4*(blockIdx.x*blockDim.x + threadIdx.x);
  if (i + 4 <= e) {
    int4 d = *(const int4*)(dst + i);
    int4 s = *(const int4*)(src + i);
    int r0 = atomicAdd(&g_deg[d.x], 1);
    int r1 = atomicAdd(&g_deg[d.y], 1);
    int r2 = atomicAdd(&g_deg[d.z], 1);
    int r3 = atomicAdd(&g_deg[d.w], 1);
    g_ell[d.x*ELLW + r0] = s.x;
    g_ell[d.y*ELLW + r1] = s.y;
    g_ell[d.z*ELLW + r2] = s.z;
    g_ell[d.w*ELLW + r3] = s.w;
  } else {
    for (int j = i; j < e; ++j) {
      int r = atomicAdd(&g_deg[dst[j]], 1);
      g_ell[dst[j]*ELLW + r] = src[j];
    }
  }
}

// ---------------- fused per-layer edge kernel (round-8 proven) ----------------
__global__ void __launch_bounds__(512) agg_k(int n, int layer){
  int tid = threadIdx.x, lane = tid & 31, warp = tid >> 5;
  int node = blockIdx.x * 16 + warp;
  if (node >= n) return;
  int base = node * ELLW;
  int deg = g_deg[node];
  float erd = g_er[node];

  int half = lane >> 4, q = lane & 15;
  const float* fb = g_feat + q*4;
  float4 acc = make_float4(0.f, 0.f, 0.f, 0.f);

  if (deg <= 32) {
    int s = 0; float v = -1e30f;
    if (lane < deg) {
      s = g_ell[base + lane];
      v = g_el[s] + erd;
      v = (v >= 0.f) ? v : 0.2f*v;
      if (layer > 0 && !g_mask[base + lane]) v = -1e9f;
    }
    float m = v;
    #pragma unroll
    for (int o = 16; o; o >>= 1) m = fmaxf(m, __shfl_xor_sync(0xffffffffu, m, o));
    float a = (lane < deg) ? expf(v - m) : 0.f;
    float se = a;
    #pragma unroll
    for (int o = 16; o; o >>= 1) se += __shfl_xor_sync(0xffffffffu, se, o);
    float alpha = a / fmaxf(se, 1e-9f);
    if (layer == 0 && lane < deg) g_mask[base + lane] = (alpha >= 0.01f) ? 1 : 0;
    if (alpha == 0.f) s = 0;

    int npair = (deg + 1) >> 1;
    int p = 0;
    for (; p + 4 <= npair; p += 4) {
      int j0 = 2*p + half, j1 = j0 + 2, j2 = j0 + 4, j3 = j0 + 6;
      int s0 = __shfl_sync(0xffffffffu, s, j0);
      int s1 = __shfl_sync(0xffffffffu, s, j1);
      int s2 = __shfl_sync(0xffffffffu, s, j2);
      int s3 = __shfl_sync(0xffffffffu, s, j3);
      float a0 = __shfl_sync(0xffffffffu, alpha, j0);
      float a1 = __shfl_sync(0xffffffffu, alpha, j1);
      float a2 = __shfl_sync(0xffffffffu, alpha, j2);
      float a3 = __shfl_sync(0xffffffffu, alpha, j3);
      float4 f0 = *(const float4*)(fb + (size_t)s0*64);
      float4 f1 = *(const float4*)(fb + (size_t)s1*64);
      float4 f2 = *(const float4*)(fb + (size_t)s2*64);
      float4 f3 = *(const float4*)(fb + (size_t)s3*64);
      acc.x = fmaf(a0, f0.x, acc.x); acc.y = fmaf(a0, f0.y, acc.y);
      acc.z = fmaf(a0, f0.z, acc.z); acc.w = fmaf(a0, f0.w, acc.w);
      acc.x = fmaf(a1, f1.x, acc.x); acc.y = fmaf(a1, f1.y, acc.y);
      acc.z = fmaf(a1, f1.z, acc.z); acc.w = fmaf(a1, f1.w, acc.w);
      acc.x = fmaf(a2, f2.x, acc.x); acc.y = fmaf(a2, f2.y, acc.y);
      acc.z = fmaf(a2, f2.z, acc.z); acc.w = fmaf(a2, f2.w, acc.w);
      acc.x = fmaf(a3, f3.x, acc.x); acc.y = fmaf(a3, f3.y, acc.y);
      acc.z = fmaf(a3, f3.z, acc.z); acc.w = fmaf(a3, f3.w, acc.w);
    }
    for (; p < npair; ++p) {
      int j = 2*p + half;
      int sj = __shfl_sync(0xffffffffu, s, j);
      float aj = __shfl_sync(0xffffffffu, alpha, j);
      float4 f = *(const float4*)(fb + (size_t)sj*64);
      acc.x = fmaf(aj, f.x, acc.x); acc.y = fmaf(aj, f.y, acc.y);
      acc.z = fmaf(aj, f.z, acc.z); acc.w = fmaf(aj, f.w, acc.w);
    }
  } else {
    int dd = (deg <= ELLW) ? deg : ELLW;
    int s0 = 0, s1 = 0; float v0 = -1e30f, v1 = -1e30f;
    if (lane < dd) {
      s0 = g_ell[base + lane];
      v0 = g_el[s0] + erd;
      v0 = (v0 >= 0.f) ? v0 : 0.2f*v0;
      if (layer > 0 && !g_mask[base + lane]) v0 = -1e9f;
    }
    if (lane + 32 < dd) {
      s1 = g_ell[base + lane + 32];
      v1 = g_el[s1] + erd;
      v1 = (v1 >= 0.f) ? v1 : 0.2f*v1;
      if (layer > 0 && !g_mask[base + lane + 32]) v1 = -1e9f;
    }
    float m = fmaxf(v0, v1);
    #pragma unroll
    for (int o = 16; o; o >>= 1) m = fmaxf(m, __shfl_xor_sync(0xffffffffu, m, o));
    float a0 = (lane < dd) ? expf(v0 - m) : 0.f;
    float a1 = (lane + 32 < dd) ? expf(v1 - m) : 0.f;
    float se = a0 + a1;
    #pragma unroll
    for (int o = 16; o; o >>= 1) se += __shfl_xor_sync(0xffffffffu, se, o);
    float inv = 1.f / fmaxf(se, 1e-9f);
    float al0 = a0 * inv, al1 = a1 * inv;
    if (layer == 0) {
      if (lane < dd)      g_mask[base + lane]      = (al0 >= 0.01f) ? 1 : 0;
      if (lane + 32 < dd) g_mask[base + lane + 32] = (al1 >= 0.01f) ? 1 : 0;
    }
    if (al0 == 0.f) s0 = 0;
    if (al1 == 0.f) s1 = 0;

    int npair = (dd + 1) >> 1;
    for (int p = 0; p < npair; ++p) {
      int j = 2*p + half;
      int sa = __shfl_sync(0xffffffffu, s0, j & 31);
      int sb2 = __shfl_sync(0xffffffffu, s1, j & 31);
      float aa = __shfl_sync(0xffffffffu, al0, j & 31);
      float ab = __shfl_sync(0xffffffffu, al1, j & 31);
      int sj   = (j < 32) ? sa : sb2;
      float aj = (j < 32) ? aa : ab;
      if (j < dd) {
        float4 f = *(const float4*)(fb + (size_t)sj*64);
        acc.x = fmaf(aj, f.x, acc.x); acc.y = fmaf(aj, f.y, acc.y);
        acc.z = fmaf(aj, f.z, acc.z); acc.w = fmaf(aj, f.w, acc.w);
      }
    }
  }

  acc.x += __shfl_xor_sync(0xffffffffu, acc.x, 16);
  acc.y += __shfl_xor_sync(0xffffffffu, acc.y, 16);
  acc.z += __shfl_xor_sync(0xffffffffu, acc.z, 16);
  acc.w += __shfl_xor_sync(0xffffffffu, acc.w, 16);
  if (half == 0) {
    float4 o;
    o.x = (acc.x > 0.f) ? acc.x : expm1f(acc.x);
    o.y = (acc.y > 0.f) ? acc.y : expm1f(acc.y);
    o.z = (acc.z > 0.f) ? acc.z : expm1f(acc.z);
    o.w = (acc.w > 0.f) ? acc.w : expm1f(acc.w);
    *(float4*)(g_fcat + (size_t)node*256 + layer*64 + q*4) = o;
  }
}

// ---------------- launch ----------------
extern "C" void kernel_launch(void* const* d_in, const int* in_sizes, int n_in,
                              void* d_out, int out_size)
{
  const float* x       = (const float*)d_in[0];
  const int*   esrc    = (const int*)  d_in[1];
  const int*   edst    = (const int*)  d_in[2];
  const float* W_embed = (const float*)d_in[3];
  const float* W_gat   = (const float*)d_in[4];
  const float* a_l     = (const float*)d_in[5];
  const float* a_r     = (const float*)d_in[6];
  const float* W0      = (const float*)d_in[7];
  const float* b0      = (const float*)d_in[8];
  const float* W1      = (const float*)d_in[9];
  const float* b1      = (const float*)d_in[10];
  const float* W2      = (const float*)d_in[11];
  const float* b2      = (const float*)d_in[12];
  float* out = (float*)d_out;

  int n = in_sizes[0] / 128;
  int e = in_sizes[1];

  float *h_ptr, *feat_ptr, *fcat_ptr, *el_ptr, *er_ptr;
  cudaGetSymbolAddress((void**)&h_ptr,    g_h);
  cudaGetSymbolAddress((void**)&feat_ptr, g_feat);
  cudaGetSymbolAddress((void**)&fcat_ptr, g_fcat);
  cudaGetSymbolAddress((void**)&el_ptr,   g_el);
  cudaGetSymbolAddress((void**)&er_ptr,   g_er);

  int tiles = (n + 63) / 64;

  // ELL build
  zero_deg_k<<<(n + 255)/256, 256>>>(n);
  build_k<<<((e+3)/4 + 255)/256, 256>>>(esrc, edst, e);

  // embed: h = tanh(x @ W_embed)
  tcg_k<128, 1, 0><<<tiles, 256>>>(x, 128, W_embed, nullptr, h_ptr, n,
                                   nullptr, nullptr, nullptr, nullptr, nullptr, nullptr);

  for (int l = 0; l < 4; ++l) {
    const float* Ain = (l == 0) ? h_ptr : (fcat_ptr + (l-1)*64);
    int lda = (l == 0) ? 64 : 256;
    tcg_k<64, 0, 1><<<tiles, 256>>>(Ain, lda, W_gat + l*64*64, nullptr, feat_ptr, n,
                                    a_l + l*64, a_r + l*64, el_ptr, er_ptr,
                                    nullptr, nullptr);
    agg_k<<<(n + 15)/16, 512>>>(n, l);
  }

  // MLP head: fcat -> 64 (relu) -> [64 (relu) -> 1 (relu), fused]
  tcg_k<256, 2, 0><<<tiles, 256>>>(fcat_ptr, 256, W0, b0, feat_ptr, n,
                                   nullptr, nullptr, nullptr, nullptr, nullptr, nullptr);
  tcg_k<64, 2, 2><<<tiles, 256>>>(feat_ptr, 64, W1, b1, out, n,
                                  nullptr, nullptr, nullptr, nullptr, W2, b2);
}

// round 15
// speedup vs baseline: 1.6116x; 1.6116x over previous
#include <cuda_runtime.h>
#include <math.h>
#include <stdint.h>

#define N_NODES 50000
#define N_EDGES 800000
#define HID 64
#define ELLW 64

// ---------------- scratch (device globals) ----------------
__device__ float g_h[N_NODES*HID];
__device__ float g_feat[N_NODES*HID];
__device__ float g_fcat[N_NODES*4*HID];
__device__ float g_el[N_NODES];
__device__ float g_er[N_NODES];
__device__ unsigned char g_mask[N_NODES*ELLW];
__device__ int g_deg[N_NODES];
__device__ int g_ell[N_NODES*ELLW];

// ---------------- tf32 split helpers ----------------
__device__ __forceinline__ void split32(float x, uint32_t& hi, uint32_t& lo){
  uint32_t xb = __float_as_uint(x);
  hi = xb & 0xFFFFE000u;                       // exact tf32 (truncation)
  lo = __float_as_uint(x - __uint_as_float(hi));
}
__device__ __forceinline__ void mma8(float* c, const uint32_t* a, const uint32_t* b){
  asm(
    "mma.sync.aligned.m16n8k8.row.col.f32.tf32.tf32.f32 "
    "{%0,%1,%2,%3}, {%4,%5,%6,%7}, {%8,%9}, {%0,%1,%2,%3};"
    : "+f"(c[0]), "+f"(c[1]), "+f"(c[2]), "+f"(c[3])
    : "r"(a[0]), "r"(a[1]), "r"(a[2]), "r"(a[3]), "r"(b[0]), "r"(b[1]));
}
__device__ __forceinline__ uint32_t smem_u32(const void* p){
  uint32_t a;
  asm("{ .reg .u64 t; cvta.to.shared.u64 t, %1; cvt.u32.u64 %0, t; }" : "=r"(a) : "l"(p));
  return a;
}
// async 16B copy with zero-fill when pred is false
__device__ __forceinline__ void cpasync16(uint32_t dst, const void* src, bool pred){
  int sz = pred ? 16 : 0;
  asm volatile("cp.async.cg.shared.global [%0], [%1], 16, %2;"
               :: "r"(dst), "l"(src), "r"(sz) : "memory");
}

// ---------------- tensor-core GEMM (mma.sync tf32 split), round-12 shape ----------------
// C[n,64] = act(A[n,K] @ W[K,64]); tile 128x64; K-chunk 64; 8 warps (4 M x 2 N).
// ACT: 0=none, 1=tanh, 2=bias+relu
// MODE: 0=plain store; 1=store + el/er dots; 2=NO store, final dot w2 -> out[n]
template<int K, int ACT, int MODE>
__global__ void __launch_bounds__(256, 4) tcg_k(const float* __restrict__ A, int lda,
    const float* __restrict__ W, const float* __restrict__ bias,
    float* __restrict__ out, int n,
    const float* __restrict__ al, const float* __restrict__ ar,
    float* __restrict__ el, float* __restrict__ er,
    const float* __restrict__ w2, const float* __restrict__ b2)
{
  __shared__ float As[128*64];   // A chunk, k-XOR-swizzled per row
  __shared__ float Ws[64*64];    // W^T: Ws[c][k], k-XOR-swizzled per c-row
  int tid = threadIdx.x, lane = tid & 31, wid = tid >> 5;
  int wm = wid & 3, wn = wid >> 2;     // warp grid 4 (M) x 2 (N)
  int gid = lane >> 2, tig = lane & 3;
  int row0 = blockIdx.x * 128;
  uint32_t as_base = smem_u32(As);

  float acc[2][4][4];
  #pragma unroll
  for (int mt = 0; mt < 2; ++mt)
    #pragma unroll
    for (int nt = 0; nt < 4; ++nt)
      #pragma unroll
      for (int i = 0; i < 4; ++i) acc[mt][nt][i] = 0.f;

  for (int kc = 0; kc < K; kc += 64) {
    __syncthreads();
    // A fill via cp.async (zero-fill beyond n): 128 rows x 64 k = 2048 float4
    #pragma unroll
    for (int j = 0; j < 8; ++j) {
      int idx = tid + 256*j;
      int r = idx >> 4, kq = (idx & 15) * 4;
      int gr = row0 + r;
      bool ok = gr < n;
      const float* src = A + (size_t)(ok ? gr : 0)*lda + kc + kq;
      cpasync16(as_base + 4*(r*64 + (kq ^ (4*(r & 7)))), src, ok);
    }
    asm volatile("cp.async.commit_group;" ::: "memory");
    // W fill (transpose; stays LDG/STS): 64 k x 64 c
    #pragma unroll
    for (int j = 0; j < 4; ++j) {
      int idx = tid + 256*j;
      int k = idx >> 4, cq = (idx & 15) * 4;
      float4 v = *(const float4*)(W + (size_t)(kc + k)*64 + cq);
      Ws[(cq+0)*64 + (k ^ (4*((cq+0) & 7)))] = v.x;
      Ws[(cq+1)*64 + (k ^ (4*((cq+1) & 7)))] = v.y;
      Ws[(cq+2)*64 + (k ^ (4*((cq+2) & 7)))] = v.z;
      Ws[(cq+3)*64 + (k ^ (4*((cq+3) & 7)))] = v.w;
    }
    asm volatile("cp.async.wait_group 0;" ::: "memory");
    __syncthreads();

    #pragma unroll
    for (int ks = 0; ks < 8; ++ks) {
      int k0 = ks * 8;
      uint32_t bh[4][2], blo[4][2];
      #pragma unroll
      for (int nt = 0; nt < 4; ++nt) {
        int c = wn*32 + nt*8 + gid;
        int m = 4*(c & 7);
        split32(Ws[c*64 + ((k0 + tig)     ^ m)], bh[nt][0], blo[nt][0]);
        split32(Ws[c*64 + ((k0 + tig + 4) ^ m)], bh[nt][1], blo[nt][1]);
      }
      #pragma unroll
      for (int mt = 0; mt < 2; ++mt) {
        int r = wm*32 + mt*16 + gid;       // (r+8)&7 == r&7, same swizzle
        int m = 4*(r & 7);
        uint32_t ah[4], alo[4];
        split32(As[r*64     + ((k0 + tig)     ^ m)], ah[0], alo[0]);
        split32(As[(r+8)*64 + ((k0 + tig)     ^ m)], ah[1], alo[1]);
        split32(As[r*64     + ((k0 + tig + 4) ^ m)], ah[2], alo[2]);
        split32(As[(r+8)*64 + ((k0 + tig + 4) ^ m)], ah[3], alo[3]);
        #pragma unroll
        for (int nt = 0; nt < 4; ++nt) {
          mma8(acc[mt][nt], ah,  bh[nt]);
          mma8(acc[mt][nt], ah,  blo[nt]);
          mma8(acc[mt][nt], alo, bh[nt]);
        }
      }
    }
  }

  // reduction scratch overlays As (done reading it)
  float* redl = As;
  float* redr = As + 128;
  if (MODE == 1 || MODE == 2) {
    __syncthreads();
    if (tid < 128) { redl[tid] = 0.f; redr[tid] = 0.f; }
    __syncthreads();
  }

  #pragma unroll
  for (int mt = 0; mt < 2; ++mt)
    #pragma unroll
    for (int h = 0; h < 2; ++h) {
      int lr = wm*32 + mt*16 + 8*h + gid;
      int r = row0 + lr;
      float pl = 0.f, pr = 0.f;
      #pragma unroll
      for (int nt = 0; nt < 4; ++nt) {
        float o0 = acc[mt][nt][2*h], o1 = acc[mt][nt][2*h + 1];
        int c0 = wn*32 + nt*8 + 2*tig;
        if (ACT == 1) { o0 = tanhf(o0); o1 = tanhf(o1); }
        if (ACT == 2) { o0 = fmaxf(o0 + bias[c0], 0.f); o1 = fmaxf(o1 + bias[c0+1], 0.f); }
        if (MODE != 2 && r < n)
          *(float2*)(out + (size_t)r*64 + c0) = make_float2(o0, o1);
        if (MODE == 1) {
          pl += o0*al[c0] + o1*al[c0+1];
          pr += o0*ar[c0] + o1*ar[c0+1];
        }
        if (MODE == 2) pl += o0*w2[c0] + o1*w2[c0+1];
      }
      if (MODE == 1 || MODE == 2) {
        pl += __shfl_xor_sync(0xffffffffu, pl, 1);
        pl += __shfl_xor_sync(0xffffffffu, pl, 2);
        if (MODE == 1) {
          pr += __shfl_xor_sync(0xffffffffu, pr, 1);
          pr += __shfl_xor_sync(0xffffffffu, pr, 2);
        }
        if (tig == 0) {
          atomicAdd(&redl[lr], pl);
          if (MODE == 1) atomicAdd(&redr[lr], pr);
        }
      }
    }

  if (MODE == 1 || MODE == 2) {
    __syncthreads();
    if (tid < 128) {
      int r = row0 + tid;
      if (r < n) {
        if (MODE == 1) { el[r] = redl[tid]; er[r] = redr[tid]; }
        else           out[r] = fmaxf(redl[tid] + b2[0], 0.f);
      }
    }
  }
}

// ---------------- ELL build ----------------
__global__ void zero_deg_k(int n){
  int i = blockIdx.x*blockDim.x + threadIdx.x;
  if (i < n) g_deg[i] = 0;
}
__global__ void build_k(const int* __restrict__ src, const int* __restrict__ dst, int e){
  int i = 4*(blockIdx.x*blockDim.x + threadIdx.x);
  if (i + 4 <= e) {
    int4 d = *(const int4*)(dst + i);
    int4 s = *(const int4*)(src + i);
    int r0 = atomicAdd(&g_deg[d.x], 1);
    int r1 = atomicAdd(&g_deg[d.y], 1);
    int r2 = atomicAdd(&g_deg[d.z], 1);
    int r3 = atomicAdd(&g_deg[d.w], 1);
    g_ell[d.x*ELLW + r0] = s.x;
    g_ell[d.y*ELLW + r1] = s.y;
    g_ell[d.z*ELLW + r2] = s.z;
    g_ell[d.w*ELLW + r3] = s.w;
  } else {
    for (int j = i; j < e; ++j) {
      int r = atomicAdd(&g_deg[dst[j]], 1);
      g_ell[dst[j]*ELLW + r] = src[j];
    }
  }
}

// ---------------- fused per-layer edge kernel (round-8 proven) ----------------
__global__ void __launch_bounds__(512) agg_k(int n, int layer){
  int tid = threadIdx.x, lane = tid & 31, warp = tid >> 5;
  int node = blockIdx.x * 16 + warp;
  if (node >= n) return;
  int base = node * ELLW;
  int deg = g_deg[node];
  float erd = g_er[node];

  int half = lane >> 4, q = lane & 15;
  const float* fb = g_feat + q*4;
  float4 acc = make_float4(0.f, 0.f, 0.f, 0.f);

  if (deg <= 32) {
    int s = 0; float v = -1e30f;
    if (lane < deg) {
      s = g_ell[base + lane];
      v = g_el[s] + erd;
      v = (v >= 0.f) ? v : 0.2f*v;
      if (layer > 0 && !g_mask[base + lane]) v = -1e9f;
    }
    float m = v;
    #pragma unroll
    for (int o = 16; o; o >>= 1) m = fmaxf(m, __shfl_xor_sync(0xffffffffu, m, o));
    float a = (lane < deg) ? expf(v - m) : 0.f;
    float se = a;
    #pragma unroll
    for (int o = 16; o; o >>= 1) se += __shfl_xor_sync(0xffffffffu, se, o);
    float alpha = a / fmaxf(se, 1e-9f);
    if (layer == 0 && lane < deg) g_mask[base + lane] = (alpha >= 0.01f) ? 1 : 0;
    if (alpha == 0.f) s = 0;

    int npair = (deg + 1) >> 1;
    int p = 0;
    for (; p + 4 <= npair; p += 4) {
      int j0 = 2*p + half, j1 = j0 + 2, j2 = j0 + 4, j3 = j0 + 6;
      int s0 = __shfl_sync(0xffffffffu, s, j0);
      int s1 = __shfl_sync(0xffffffffu, s, j1);
      int s2 = __shfl_sync(0xffffffffu, s, j2);
      int s3 = __shfl_sync(0xffffffffu, s, j3);
      float a0 = __shfl_sync(0xffffffffu, alpha, j0);
      float a1 = __shfl_sync(0xffffffffu, alpha, j1);
      float a2 = __shfl_sync(0xffffffffu, alpha, j2);
      float a3 = __shfl_sync(0xffffffffu, alpha, j3);
      float4 f0 = *(const float4*)(fb + (size_t)s0*64);
      float4 f1 = *(const float4*)(fb + (size_t)s1*64);
      float4 f2 = *(const float4*)(fb + (size_t)s2*64);
      float4 f3 = *(const float4*)(fb + (size_t)s3*64);
      acc.x = fmaf(a0, f0.x, acc.x); acc.y = fmaf(a0, f0.y, acc.y);
      acc.z = fmaf(a0, f0.z, acc.z); acc.w = fmaf(a0, f0.w, acc.w);
      acc.x = fmaf(a1, f1.x, acc.x); acc.y = fmaf(a1, f1.y, acc.y);
      acc.z = fmaf(a1, f1.z, acc.z); acc.w = fmaf(a1, f1.w, acc.w);
      acc.x = fmaf(a2, f2.x, acc.x); acc.y = fmaf(a2, f2.y, acc.y);
      acc.z = fmaf(a2, f2.z, acc.z); acc.w = fmaf(a2, f2.w, acc.w);
      acc.x = fmaf(a3, f3.x, acc.x); acc.y = fmaf(a3, f3.y, acc.y);
      acc.z = fmaf(a3, f3.z, acc.z); acc.w = fmaf(a3, f3.w, acc.w);
    }
    for (; p < npair; ++p) {
      int j = 2*p + half;
      int sj = __shfl_sync(0xffffffffu, s, j);
      float aj = __shfl_sync(0xffffffffu, alpha, j);
      float4 f = *(const float4*)(fb + (size_t)sj*64);
      acc.x = fmaf(aj, f.x, acc.x); acc.y = fmaf(aj, f.y, acc.y);
      acc.z = fmaf(aj, f.z, acc.z); acc.w = fmaf(aj, f.w, acc.w);
    }
  } else {
    int dd = (deg <= ELLW) ? deg : ELLW;
    int s0 = 0, s1 = 0; float v0 = -1e30f, v1 = -1e30f;
    if (lane < dd) {
      s0 = g_ell[base + lane];
      v0 = g_el[s0] + erd;
      v0 = (v0 >= 0.f) ? v0 : 0.2f*v0;
      if (layer > 0 && !g_mask[base + lane]) v0 = -1e9f;
    }
    if (lane + 32 < dd) {
      s1 = g_ell[base + lane + 32];
      v1 = g_el[s1] + erd;
      v1 = (v1 >= 0.f) ? v1 : 0.2f*v1;
      if (layer > 0 && !g_mask[base + lane + 32]) v1 = -1e9f;
    }
    float m = fmaxf(v0, v1);
    #pragma unroll
    for (int o = 16; o; o >>= 1) m = fmaxf(m, __shfl_xor_sync(0xffffffffu, m, o));
    float a0 = (lane < dd) ? expf(v0 - m) : 0.f;
    float a1 = (lane + 32 < dd) ? expf(v1 - m) : 0.f;
    float se = a0 + a1;
    #pragma unroll
    for (int o = 16; o; o >>= 1) se += __shfl_xor_sync(0xffffffffu, se, o);
    float inv = 1.f / fmaxf(se, 1e-9f);
    float al0 = a0 * inv, al1 = a1 * inv;
    if (layer == 0) {
      if (lane < dd)      g_mask[base + lane]      = (al0 >= 0.01f) ? 1 : 0;
      if (lane + 32 < dd) g_mask[base + lane + 32] = (al1 >= 0.01f) ? 1 : 0;
    }
    if (al0 == 0.f) s0 = 0;
    if (al1 == 0.f) s1 = 0;

    int npair = (dd + 1) >> 1;
    for (int p = 0; p < npair; ++p) {
      int j = 2*p + half;
      int sa = __shfl_sync(0xffffffffu, s0, j & 31);
      int sb2 = __shfl_sync(0xffffffffu, s1, j & 31);
      float aa = __shfl_sync(0xffffffffu, al0, j & 31);
      float ab = __shfl_sync(0xffffffffu, al1, j & 31);
      int sj   = (j < 32) ? sa : sb2;
      float aj = (j < 32) ? aa : ab;
      if (j < dd) {
        float4 f = *(const float4*)(fb + (size_t)sj*64);
        acc.x = fmaf(aj, f.x, acc.x); acc.y = fmaf(aj, f.y, acc.y);
        acc.z = fmaf(aj, f.z, acc.z); acc.w = fmaf(aj, f.w, acc.w);
      }
    }
  }

  acc.x += __shfl_xor_sync(0xffffffffu, acc.x, 16);
  acc.y += __shfl_xor_sync(0xffffffffu, acc.y, 16);
  acc.z += __shfl_xor_sync(0xffffffffu, acc.z, 16);
  acc.w += __shfl_xor_sync(0xffffffffu, acc.w, 16);
  if (half == 0) {
    float4 o;
    o.x = (acc.x > 0.f) ? acc.x : expm1f(acc.x);
    o.y = (acc.y > 0.f) ? acc.y : expm1f(acc.y);
    o.z = (acc.z > 0.f) ? acc.z : expm1f(acc.z);
    o.w = (acc.w > 0.f) ? acc.w : expm1f(acc.w);
    *(float4*)(g_fcat + (size_t)node*256 + layer*64 + q*4) = o;
  }
}

// ---------------- launch ----------------
extern "C" void kernel_launch(void* const* d_in, const int* in_sizes, int n_in,
                              void* d_out, int out_size)
{
  const float* x       = (const float*)d_in[0];
  const int*   esrc    = (const int*)  d_in[1];
  const int*   edst    = (const int*)  d_in[2];
  const float* W_embed = (const float*)d_in[3];
  const float* W_gat   = (const float*)d_in[4];
  const float* a_l     = (const float*)d_in[5];
  const float* a_r     = (const float*)d_in[6];
  const float* W0      = (const float*)d_in[7];
  const float* b0      = (const float*)d_in[8];
  const float* W1      = (const float*)d_in[9];
  const float* b1      = (const float*)d_in[10];
  const float* W2      = (const float*)d_in[11];
  const float* b2      = (const float*)d_in[12];
  float* out = (float*)d_out;

  int n = in_sizes[0] / 128;
  int e = in_sizes[1];

  float *h_ptr, *feat_ptr, *fcat_ptr, *el_ptr, *er_ptr;
  cudaGetSymbolAddress((void**)&h_ptr,    g_h);
  cudaGetSymbolAddress((void**)&feat_ptr, g_feat);
  cudaGetSymbolAddress((void**)&fcat_ptr, g_fcat);
  cudaGetSymbolAddress((void**)&el_ptr,   g_el);
  cudaGetSymbolAddress((void**)&er_ptr,   g_er);

  int tiles = (n + 127) / 128;

  // ELL build
  zero_deg_k<<<(n + 255)/256, 256>>>(n);
  build_k<<<((e+3)/4 + 255)/256, 256>>>(esrc, edst, e);

  // embed: h = tanh(x @ W_embed)
  tcg_k<128, 1, 0><<<tiles, 256>>>(x, 128, W_embed, nullptr, h_ptr, n,
                                   nullptr, nullptr, nullptr, nullptr, nullptr, nullptr);

  for (int l = 0; l < 4; ++l) {
    const float* Ain = (l == 0) ? h_ptr : (fcat_ptr + (l-1)*64);
    int lda = (l == 0) ? 64 : 256;
    tcg_k<64, 0, 1><<<tiles, 256>>>(Ain, lda, W_gat + l*64*64, nullptr, feat_ptr, n,
                                    a_l + l*64, a_r + l*64, el_ptr, er_ptr,
                                    nullptr, nullptr);
    agg_k<<<(n + 15)/16, 512>>>(n, l);
  }

  // MLP head: fcat -> 64 (relu) -> [64 (relu) -> 1 (relu), fused]
  tcg_k<256, 2, 0><<<tiles, 256>>>(fcat_ptr, 256, W0, b0, feat_ptr, n,
                                   nullptr, nullptr, nullptr, nullptr, nullptr, nullptr);
  tcg_k<64, 2, 2><<<tiles, 256>>>(feat_ptr, 64, W1, b1, out, n,
                                  nullptr, nullptr, nullptr, nullptr, W2, b2);
}

// round 16
// speedup vs baseline: 1.7186x; 1.0664x over previous
#include <cuda_runtime.h>
#include <math.h>
#include <stdint.h>

#define N_NODES 50000
#define N_EDGES 800000
#define HID 64
#define ELLW 64

// ---------------- scratch (device globals) ----------------
__device__ float g_h[N_NODES*HID];
__device__ float g_feat[N_NODES*HID];
__device__ float g_fcat[N_NODES*4*HID];
__device__ float g_el[N_NODES];
__device__ float g_er[N_NODES];
__device__ unsigned char g_mask[N_NODES*ELLW];
__device__ int g_deg[N_NODES];
__device__ int g_ell[N_NODES*ELLW];

// ---------------- tf32 split helpers ----------------
__device__ __forceinline__ void split32(float x, uint32_t& hi, uint32_t& lo){
  uint32_t xb = __float_as_uint(x);
  hi = xb & 0xFFFFE000u;                       // exact tf32 (truncation)
  lo = __float_as_uint(x - __uint_as_float(hi));
}
__device__ __forceinline__ void mma8(float* c, const uint32_t* a, const uint32_t* b){
  asm(
    "mma.sync.aligned.m16n8k8.row.col.f32.tf32.tf32.f32 "
    "{%0,%1,%2,%3}, {%4,%5,%6,%7}, {%8,%9}, {%0,%1,%2,%3};"
    : "+f"(c[0]), "+f"(c[1]), "+f"(c[2]), "+f"(c[3])
    : "r"(a[0]), "r"(a[1]), "r"(a[2]), "r"(a[3]), "r"(b[0]), "r"(b[1]));
}
__device__ __forceinline__ uint32_t smem_u32(const void* p){
  uint32_t a;
  asm("{ .reg .u64 t; cvta.to.shared.u64 t, %1; cvt.u32.u64 %0, t; }" : "=r"(a) : "l"(p));
  return a;
}
// async 16B copy with zero-fill when pred is false
__device__ __forceinline__ void cpasync16(uint32_t dst, const void* src, bool pred){
  int sz = pred ? 16 : 0;
  asm volatile("cp.async.cg.shared.global [%0], [%1], 16, %2;"
               :: "r"(dst), "l"(src), "r"(sz) : "memory");
}
// monotone order-preserving float<->uint encoding (for REDUX max incl. negatives)
__device__ __forceinline__ unsigned fenc(float x){
  unsigned u = __float_as_uint(x);
  return (u & 0x80000000u) ? ~u : (u | 0x80000000u);
}
__device__ __forceinline__ float fdec(unsigned u){
  return __uint_as_float((u & 0x80000000u) ? (u ^ 0x80000000u) : ~u);
}

// ---------------- tensor-core GEMM (round-15 winner, unchanged) ----------------
// C[n,64] = act(A[n,K] @ W[K,64]); tile 128x64; K-chunk 64; 8 warps (4 M x 2 N).
// ACT: 0=none, 1=tanh, 2=bias+relu
// MODE: 0=plain store; 1=store + el/er dots; 2=NO store, final dot w2 -> out[n]
template<int K, int ACT, int MODE>
__global__ void __launch_bounds__(256, 4) tcg_k(const float* __restrict__ A, int lda,
    const float* __restrict__ W, const float* __restrict__ bias,
    float* __restrict__ out, int n,
    const float* __restrict__ al, const float* __restrict__ ar,
    float* __restrict__ el, float* __restrict__ er,
    const float* __restrict__ w2, const float* __restrict__ b2)
{
  __shared__ float As[128*64];   // A chunk, k-XOR-swizzled per row
  __shared__ float Ws[64*64];    // W^T: Ws[c][k], k-XOR-swizzled per c-row
  int tid = threadIdx.x, lane = tid & 31, wid = tid >> 5;
  int wm = wid & 3, wn = wid >> 2;     // warp grid 4 (M) x 2 (N)
  int gid = lane >> 2, tig = lane & 3;
  int row0 = blockIdx.x * 128;
  uint32_t as_base = smem_u32(As);

  float acc[2][4][4];
  #pragma unroll
  for (int mt = 0; mt < 2; ++mt)
    #pragma unroll
    for (int nt = 0; nt < 4; ++nt)
      #pragma unroll
      for (int i = 0; i < 4; ++i) acc[mt][nt][i] = 0.f;

  for (int kc = 0; kc < K; kc += 64) {
    __syncthreads();
    #pragma unroll
    for (int j = 0; j < 8; ++j) {
      int idx = tid + 256*j;
      int r = idx >> 4, kq = (idx & 15) * 4;
      int gr = row0 + r;
      bool ok = gr < n;
      const float* src = A + (size_t)(ok ? gr : 0)*lda + kc + kq;
      cpasync16(as_base + 4*(r*64 + (kq ^ (4*(r & 7)))), src, ok);
    }
    asm volatile("cp.async.commit_group;" ::: "memory");
    #pragma unroll
    for (int j = 0; j < 4; ++j) {
      int idx = tid + 256*j;
      int k = idx >> 4, cq = (idx & 15) * 4;
      float4 v = *(const float4*)(W + (size_t)(kc + k)*64 + cq);
      Ws[(cq+0)*64 + (k ^ (4*((cq+0) & 7)))] = v.x;
      Ws[(cq+1)*64 + (k ^ (4*((cq+1) & 7)))] = v.y;
      Ws[(cq+2)*64 + (k ^ (4*((cq+2) & 7)))] = v.z;
      Ws[(cq+3)*64 + (k ^ (4*((cq+3) & 7)))] = v.w;
    }
    asm volatile("cp.async.wait_group 0;" ::: "memory");
    __syncthreads();

    #pragma unroll
    for (int ks = 0; ks < 8; ++ks) {
      int k0 = ks * 8;
      uint32_t bh[4][2], blo[4][2];
      #pragma unroll
      for (int nt = 0; nt < 4; ++nt) {
        int c = wn*32 + nt*8 + gid;
        int m = 4*(c & 7);
        split32(Ws[c*64 + ((k0 + tig)     ^ m)], bh[nt][0], blo[nt][0]);
        split32(Ws[c*64 + ((k0 + tig + 4) ^ m)], bh[nt][1], blo[nt][1]);
      }
      #pragma unroll
      for (int mt = 0; mt < 2; ++mt) {
        int r = wm*32 + mt*16 + gid;
        int m = 4*(r & 7);
        uint32_t ah[4], alo[4];
        split32(As[r*64     + ((k0 + tig)     ^ m)], ah[0], alo[0]);
        split32(As[(r+8)*64 + ((k0 + tig)     ^ m)], ah[1], alo[1]);
        split32(As[r*64     + ((k0 + tig + 4) ^ m)], ah[2], alo[2]);
        split32(As[(r+8)*64 + ((k0 + tig + 4) ^ m)], ah[3], alo[3]);
        #pragma unroll
        for (int nt = 0; nt < 4; ++nt) {
          mma8(acc[mt][nt], ah,  bh[nt]);
          mma8(acc[mt][nt], ah,  blo[nt]);
          mma8(acc[mt][nt], alo, bh[nt]);
        }
      }
    }
  }

  float* redl = As;
  float* redr = As + 128;
  if (MODE == 1 || MODE == 2) {
    __syncthreads();
    if (tid < 128) { redl[tid] = 0.f; redr[tid] = 0.f; }
    __syncthreads();
  }

  #pragma unroll
  for (int mt = 0; mt < 2; ++mt)
    #pragma unroll
    for (int h = 0; h < 2; ++h) {
      int lr = wm*32 + mt*16 + 8*h + gid;
      int r = row0 + lr;
      float pl = 0.f, pr = 0.f;
      #pragma unroll
      for (int nt = 0; nt < 4; ++nt) {
        float o0 = acc[mt][nt][2*h], o1 = acc[mt][nt][2*h + 1];
        int c0 = wn*32 + nt*8 + 2*tig;
        if (ACT == 1) { o0 = tanhf(o0); o1 = tanhf(o1); }
        if (ACT == 2) { o0 = fmaxf(o0 + bias[c0], 0.f); o1 = fmaxf(o1 + bias[c0+1], 0.f); }
        if (MODE != 2 && r < n)
          *(float2*)(out + (size_t)r*64 + c0) = make_float2(o0, o1);
        if (MODE == 1) {
          pl += o0*al[c0] + o1*al[c0+1];
          pr += o0*ar[c0] + o1*ar[c0+1];
        }
        if (MODE == 2) pl += o0*w2[c0] + o1*w2[c0+1];
      }
      if (MODE == 1 || MODE == 2) {
        pl += __shfl_xor_sync(0xffffffffu, pl, 1);
        pl += __shfl_xor_sync(0xffffffffu, pl, 2);
        if (MODE == 1) {
          pr += __shfl_xor_sync(0xffffffffu, pr, 1);
          pr += __shfl_xor_sync(0xffffffffu, pr, 2);
        }
        if (tig == 0) {
          atomicAdd(&redl[lr], pl);
          if (MODE == 1) atomicAdd(&redr[lr], pr);
        }
      }
    }

  if (MODE == 1 || MODE == 2) {
    __syncthreads();
    if (tid < 128) {
      int r = row0 + tid;
      if (r < n) {
        if (MODE == 1) { el[r] = redl[tid]; er[r] = redr[tid]; }
        else           out[r] = fmaxf(redl[tid] + b2[0], 0.f);
      }
    }
  }
}

// ---------------- ELL build ----------------
__global__ void zero_deg_k(int n){
  int i = blockIdx.x*blockDim.x + threadIdx.x;
  if (i < n) g_deg[i] = 0;
}
__global__ void build_k(const int* __restrict__ src, const int* __restrict__ dst, int e){
  int i = 4*(blockIdx.x*blockDim.x + threadIdx.x);
  if (i + 4 <= e) {
    int4 d = *(const int4*)(dst + i);
    int4 s = *(const int4*)(src + i);
    int r0 = atomicAdd(&g_deg[d.x], 1);
    int r1 = atomicAdd(&g_deg[d.y], 1);
    int r2 = atomicAdd(&g_deg[d.z], 1);
    int r3 = atomicAdd(&g_deg[d.w], 1);
    g_ell[d.x*ELLW + r0] = s.x;
    g_ell[d.y*ELLW + r1] = s.y;
    g_ell[d.z*ELLW + r2] = s.z;
    g_ell[d.w*ELLW + r3] = s.w;
  } else {
    for (int j = i; j < e; ++j) {
      int r = atomicAdd(&g_deg[dst[j]], 1);
      g_ell[dst[j]*ELLW + r] = src[j];
    }
  }
}

// ---------------- fused per-layer edge kernel: REDUX max + smem-staged gather ----------------
__global__ void __launch_bounds__(512) agg_k(int n, int layer){
  __shared__ int   s_sh[16][32];
  __shared__ float a_sh[16][32];
  int tid = threadIdx.x, lane = tid & 31, warp = tid >> 5;
  int node = blockIdx.x * 16 + warp;
  if (node >= n) return;
  int base = node * ELLW;
  int deg = g_deg[node];
  float erd = g_er[node];

  int half = lane >> 4, q = lane & 15;
  const float* fb = g_feat + q*4;
  float4 acc = make_float4(0.f, 0.f, 0.f, 0.f);

  if (deg <= 32) {
    int s = 0; float v = -1e30f;
    if (lane < deg) {
      s = g_ell[base + lane];
      v = g_el[s] + erd;
      v = (v >= 0.f) ? v : 0.2f*v;
      if (layer > 0 && !g_mask[base + lane]) v = -1e9f;
    }
    // segment max via hardware REDUX on monotone encoding
    float m = fdec(__reduce_max_sync(0xffffffffu, fenc(v)));
    float a = (lane < deg) ? expf(v - m) : 0.f;
    float se = a;
    #pragma unroll
    for (int o = 16; o; o >>= 1) se += __shfl_xor_sync(0xffffffffu, se, o);
    float alpha = a / fmaxf(se, 1e-9f);
    if (layer == 0 && lane < deg) g_mask[base + lane] = (alpha >= 0.01f) ? 1 : 0;
    if (alpha == 0.f) s = 0;   // dead loads hit feat[0] (L1-hot)

    // park (s, alpha) in smem; gather addressing decouples from shuffles
    s_sh[warp][lane] = s;
    a_sh[warp][lane] = alpha;
    __syncwarp();

    int npair = (deg + 1) >> 1;
    int p = 0;
    for (; p + 4 <= npair; p += 4) {
      int j0 = 2*p + half, j1 = j0 + 2, j2 = j0 + 4, j3 = j0 + 6;
      int s0 = s_sh[warp][j0], s1 = s_sh[warp][j1];
      int s2 = s_sh[warp][j2], s3 = s_sh[warp][j3];
      float a0 = a_sh[warp][j0], a1 = a_sh[warp][j1];
      float a2 = a_sh[warp][j2], a3 = a_sh[warp][j3];
      float4 f0 = *(const float4*)(fb + (size_t)s0*64);
      float4 f1 = *(const float4*)(fb + (size_t)s1*64);
      float4 f2 = *(const float4*)(fb + (size_t)s2*64);
      float4 f3 = *(const float4*)(fb + (size_t)s3*64);
      acc.x = fmaf(a0, f0.x, acc.x); acc.y = fmaf(a0, f0.y, acc.y);
      acc.z = fmaf(a0, f0.z, acc.z); acc.w = fmaf(a0, f0.w, acc.w);
      acc.x = fmaf(a1, f1.x, acc.x); acc.y = fmaf(a1, f1.y, acc.y);
      acc.z = fmaf(a1, f1.z, acc.z); acc.w = fmaf(a1, f1.w, acc.w);
      acc.x = fmaf(a2, f2.x, acc.x); acc.y = fmaf(a2, f2.y, acc.y);
      acc.z = fmaf(a2, f2.z, acc.z); acc.w = fmaf(a2, f2.w, acc.w);
      acc.x = fmaf(a3, f3.x, acc.x); acc.y = fmaf(a3, f3.y, acc.y);
      acc.z = fmaf(a3, f3.z, acc.z); acc.w = fmaf(a3, f3.w, acc.w);
    }
    for (; p < npair; ++p) {
      int j = 2*p + half;
      int sj = s_sh[warp][j];
      float aj = a_sh[warp][j];
      float4 f = *(const float4*)(fb + (size_t)sj*64);
      acc.x = fmaf(aj, f.x, acc.x); acc.y = fmaf(aj, f.y, acc.y);
      acc.z = fmaf(aj, f.z, acc.z); acc.w = fmaf(aj, f.w, acc.w);
    }
  } else {
    // deg in (32, 64]: rare fallback, shuffle-based (unchanged)
    int dd = (deg <= ELLW) ? deg : ELLW;
    int s0 = 0, s1 = 0; float v0 = -1e30f, v1 = -1e30f;
    if (lane < dd) {
      s0 = g_ell[base + lane];
      v0 = g_el[s0] + erd;
      v0 = (v0 >= 0.f) ? v0 : 0.2f*v0;
      if (layer > 0 && !g_mask[base + lane]) v0 = -1e9f;
    }
    if (lane + 32 < dd) {
      s1 = g_ell[base + lane + 32];
      v1 = g_el[s1] + erd;
      v1 = (v1 >= 0.f) ? v1 : 0.2f*v1;
      if (layer > 0 && !g_mask[base + lane + 32]) v1 = -1e9f;
    }
    float m = fdec(__reduce_max_sync(0xffffffffu, fenc(fmaxf(v0, v1))));
    float a0 = (lane < dd) ? expf(v0 - m) : 0.f;
    float a1 = (lane + 32 < dd) ? expf(v1 - m) : 0.f;
    float se = a0 + a1;
    #pragma unroll
    for (int o = 16; o; o >>= 1) se += __shfl_xor_sync(0xffffffffu, se, o);
    float inv = 1.f / fmaxf(se, 1e-9f);
    float al0 = a0 * inv, al1 = a1 * inv;
    if (layer == 0) {
      if (lane < dd)      g_mask[base + lane]      = (al0 >= 0.01f) ? 1 : 0;
      if (lane + 32 < dd) g_mask[base + lane + 32] = (al1 >= 0.01f) ? 1 : 0;
    }
    if (al0 == 0.f) s0 = 0;
    if (al1 == 0.f) s1 = 0;

    int npair = (dd + 1) >> 1;
    for (int p = 0; p < npair; ++p) {
      int j = 2*p + half;
      int sa = __shfl_sync(0xffffffffu, s0, j & 31);
      int sb2 = __shfl_sync(0xffffffffu, s1, j & 31);
      float aa = __shfl_sync(0xffffffffu, al0, j & 31);
      float ab = __shfl_sync(0xffffffffu, al1, j & 31);
      int sj   = (j < 32) ? sa : sb2;
      float aj = (j < 32) ? aa : ab;
      if (j < dd) {
        float4 f = *(const float4*)(fb + (size_t)sj*64);
        acc.x = fmaf(aj, f.x, acc.x); acc.y = fmaf(aj, f.y, acc.y);
        acc.z = fmaf(aj, f.z, acc.z); acc.w = fmaf(aj, f.w, acc.w);
      }
    }
  }

  acc.x += __shfl_xor_sync(0xffffffffu, acc.x, 16);
  acc.y += __shfl_xor_sync(0xffffffffu, acc.y, 16);
  acc.z += __shfl_xor_sync(0xffffffffu, acc.z, 16);
  acc.w += __shfl_xor_sync(0xffffffffu, acc.w, 16);
  if (half == 0) {
    float4 o;
    o.x = (acc.x > 0.f) ? acc.x : expm1f(acc.x);
    o.y = (acc.y > 0.f) ? acc.y : expm1f(acc.y);
    o.z = (acc.z > 0.f) ? acc.z : expm1f(acc.z);
    o.w = (acc.w > 0.f) ? acc.w : expm1f(acc.w);
    *(float4*)(g_fcat + (size_t)node*256 + layer*64 + q*4) = o;
  }
}

// ---------------- launch ----------------
extern "C" void kernel_launch(void* const* d_in, const int* in_sizes, int n_in,
                              void* d_out, int out_size)
{
  const float* x       = (const float*)d_in[0];
  const int*   esrc    = (const int*)  d_in[1];
  const int*   edst    = (const int*)  d_in[2];
  const float* W_embed = (const float*)d_in[3];
  const float* W_gat   = (const float*)d_in[4];
  const float* a_l     = (const float*)d_in[5];
  const float* a_r     = (const float*)d_in[6];
  const float* W0      = (const float*)d_in[7];
  const float* b0      = (const float*)d_in[8];
  const float* W1      = (const float*)d_in[9];
  const float* b1      = (const float*)d_in[10];
  const float* W2      = (const float*)d_in[11];
  const float* b2      = (const float*)d_in[12];
  float* out = (float*)d_out;

  int n = in_sizes[0] / 128;
  int e = in_sizes[1];

  float *h_ptr, *feat_ptr, *fcat_ptr, *el_ptr, *er_ptr;
  cudaGetSymbolAddress((void**)&h_ptr,    g_h);
  cudaGetSymbolAddress((void**)&feat_ptr, g_feat);
  cudaGetSymbolAddress((void**)&fcat_ptr, g_fcat);
  cudaGetSymbolAddress((void**)&el_ptr,   g_el);
  cudaGetSymbolAddress((void**)&er_ptr,   g_er);

  int tiles = (n + 127) / 128;

  // ELL build
  zero_deg_k<<<(n + 255)/256, 256>>>(n);
  build_k<<<((e+3)/4 + 255)/256, 256>>>(esrc, edst, e);

  // embed: h = tanh(x @ W_embed)
  tcg_k<128, 1, 0><<<tiles, 256>>>(x, 128, W_embed, nullptr, h_ptr, n,
                                   nullptr, nullptr, nullptr, nullptr, nullptr, nullptr);

  for (int l = 0; l < 4; ++l) {
    const float* Ain = (l == 0) ? h_ptr : (fcat_ptr + (l-1)*64);
    int lda = (l == 0) ? 64 : 256;
    tcg_k<64, 0, 1><<<tiles, 256>>>(Ain, lda, W_gat + l*64*64, nullptr, feat_ptr, n,
                                    a_l + l*64, a_r + l*64, el_ptr, er_ptr,
                                    nullptr, nullptr);
    agg_k<<<(n + 15)/16, 512>>>(n, l);
  }

  // MLP head: fcat -> 64 (relu) -> [64 (relu) -> 1 (relu), fused]
  tcg_k<256, 2, 0><<<tiles, 256>>>(fcat_ptr, 256, W0, b0, feat_ptr, n,
                                   nullptr, nullptr, nullptr, nullptr, nullptr, nullptr);
  tcg_k<64, 2, 2><<<tiles, 256>>>(feat_ptr, 64, W1, b1, out, n,
                                  nullptr, nullptr, nullptr, nullptr, W2, b2);
}